// round 1
// baseline (speedup 1.0000x reference)
#include <cuda_runtime.h>

#define NUSERS 40000
#define NITEMS 16384
#define MAXNNZ 1000000
#define BB 64
#define LAMBDA 500.0f
#define TOLER 1e-6f
#define MAX_ITER 30

// ---------------- device global scratch (no allocations allowed) ----------------
__device__ int    g_row_cnt[NUSERS];
__device__ int    g_row_ptr[NUSERS + 1];
__device__ int    g_row_off[NUSERS];
__device__ int    g_col_cnt[NITEMS];
__device__ int    g_col_ptr[NITEMS + 1];
__device__ int    g_col_off[NITEMS];
__device__ int    g_csr_col[MAXNNZ];
__device__ float  g_csr_val[MAXNNZ];
__device__ int    g_csc_row[MAXNNZ];
__device__ float  g_csc_val[MAXNNZ];

__device__ float  g_tmp[NUSERS * BB];     // X @ V          (users x 64)
__device__ float  g_Xt [NITEMS * BB];     // X_batch^T      (items x 64)
__device__ float  g_X  [NITEMS * BB];     // CG solution
__device__ float  g_R  [NITEMS * BB];
__device__ float  g_P  [NITEMS * BB];
__device__ float  g_AP [NITEMS * BB];

__device__ double g_Rs_old[BB];
__device__ double g_Rs_new[BB];
__device__ double g_pAP[BB];
__device__ float  g_beta[BB];
__device__ int    g_done;

// ---------------- init: zero everything that needs zeroing ----------------
__global__ void k_init() {
    int i = blockIdx.x * blockDim.x + threadIdx.x;   // 4096*256 = 1048576 threads
    if (i < NITEMS * BB) g_X[i] = 0.0f;
    if (i < NUSERS)      g_row_cnt[i] = 0;
    if (i < NITEMS)      g_col_cnt[i] = 0;
    if (i < BB) { g_Rs_old[i] = 0.0; g_Rs_new[i] = 0.0; g_pAP[i] = 0.0; }
    if (i == 0) g_done = 0;
}

// ---------------- histogram of rows and cols ----------------
__global__ void k_hist(const int* __restrict__ rows, const int* __restrict__ cols, int nnz) {
    for (int k = blockIdx.x * blockDim.x + threadIdx.x; k < nnz; k += gridDim.x * blockDim.x) {
        atomicAdd(&g_row_cnt[rows[k]], 1);
        atomicAdd(&g_col_cnt[cols[k]], 1);
    }
}

// ---------------- single-block exclusive scan (warp shuffle) ----------------
__global__ void k_scan(int which) {          // which==0: rows, 1: cols
    const int* cnt = which ? g_col_cnt : g_row_cnt;
    int*       ptr = which ? g_col_ptr : g_row_ptr;
    int*       off = which ? g_col_off : g_row_off;
    const int  n   = which ? NITEMS    : NUSERS;

    __shared__ int wsum[32];
    __shared__ int s_carry;
    int tid  = threadIdx.x;            // 1024 threads
    int lane = tid & 31, w = tid >> 5;
    if (tid == 0) s_carry = 0;
    __syncthreads();

    for (int base = 0; base < n; base += 1024) {
        int i = base + tid;
        int v = (i < n) ? cnt[i] : 0;
        int x = v;
        #pragma unroll
        for (int s = 1; s < 32; s <<= 1) {
            int t = __shfl_up_sync(0xffffffffu, x, s);
            if (lane >= s) x += t;
        }
        if (lane == 31) wsum[w] = x;
        __syncthreads();
        if (w == 0) {
            int y = wsum[lane];
            #pragma unroll
            for (int s = 1; s < 32; s <<= 1) {
                int t = __shfl_up_sync(0xffffffffu, y, s);
                if (lane >= s) y += t;
            }
            wsum[lane] = y;
        }
        __syncthreads();
        int warpoffset = (w == 0) ? 0 : wsum[w - 1];
        int excl = s_carry + warpoffset + x - v;
        if (i < n) { ptr[i] = excl; off[i] = excl; }
        __syncthreads();
        if (tid == 0) s_carry += wsum[31];
        __syncthreads();
    }
    if (tid == 0) ptr[n] = s_carry;
}

// ---------------- scatter into CSR and CSC ----------------
__global__ void k_scatter(const int* __restrict__ rows, const int* __restrict__ cols,
                          const float* __restrict__ vals, int nnz) {
    for (int k = blockIdx.x * blockDim.x + threadIdx.x; k < nnz; k += gridDim.x * blockDim.x) {
        int r = rows[k]; int c = cols[k]; float v = vals[k];
        int p = atomicAdd(&g_row_off[r], 1);
        g_csr_col[p] = c; g_csr_val[p] = v;
        int q = atomicAdd(&g_col_off[c], 1);
        g_csc_row[q] = r; g_csc_val[q] = v;
    }
}

// ---------------- transpose X_batch (64 x 16384) -> Xt (16384 x 64) ----------------
__global__ void k_transpose(const float* __restrict__ Xb) {
    int t = blockIdx.x * blockDim.x + threadIdx.x;   // 1048576
    int item = t >> 6, b = t & 63;
    g_Xt[t] = __ldg(&Xb[b * NITEMS + item]);
}

// ---------------- SpMM: tmp = X @ V (warp per user row) ----------------
// src: 0 -> V = g_Xt, 1 -> V = g_P
__global__ void k_spmm_csr(int src) {
    if (g_done) return;
    const float* __restrict__ V = src ? g_P : g_Xt;
    int gw   = (blockIdx.x * blockDim.x + threadIdx.x) >> 5;  // 40000 warps exactly
    int lane = threadIdx.x & 31;
    int s = g_row_ptr[gw], e = g_row_ptr[gw + 1];
    float2 acc0 = {0.f, 0.f}, acc1 = {0.f, 0.f};
    int j = s;
    for (; j + 1 < e; j += 2) {
        int   c0 = g_csr_col[j],     c1 = g_csr_col[j + 1];
        float v0 = g_csr_val[j],     v1 = g_csr_val[j + 1];
        float2 q0 = *(const float2*)(V + c0 * BB + 2 * lane);
        float2 q1 = *(const float2*)(V + c1 * BB + 2 * lane);
        acc0.x += v0 * q0.x; acc0.y += v0 * q0.y;
        acc1.x += v1 * q1.x; acc1.y += v1 * q1.y;
    }
    if (j < e) {
        int c = g_csr_col[j]; float v = g_csr_val[j];
        float2 q = *(const float2*)(V + c * BB + 2 * lane);
        acc0.x += v * q.x; acc0.y += v * q.y;
    }
    float2 o = {acc0.x + acc1.x, acc0.y + acc1.y};
    *(float2*)(g_tmp + gw * BB + 2 * lane) = o;
}

// ---------------- SpMM: out = X^T @ tmp  (+ lambda*P, + dot(P,AP)) ----------------
template <bool AP_MODE>
__global__ void k_spmm_csc() {
    if (g_done) return;
    int gw   = (blockIdx.x * blockDim.x + threadIdx.x) >> 5;  // 16384 warps exactly
    int lane = threadIdx.x & 31;
    int s = g_col_ptr[gw], e = g_col_ptr[gw + 1];
    float2 acc0 = {0.f, 0.f}, acc1 = {0.f, 0.f};
    int j = s;
    for (; j + 1 < e; j += 2) {
        int   r0 = g_csc_row[j],     r1 = g_csc_row[j + 1];
        float v0 = g_csc_val[j],     v1 = g_csc_val[j + 1];
        float2 q0 = *(const float2*)(g_tmp + r0 * BB + 2 * lane);
        float2 q1 = *(const float2*)(g_tmp + r1 * BB + 2 * lane);
        acc0.x += v0 * q0.x; acc0.y += v0 * q0.y;
        acc1.x += v1 * q1.x; acc1.y += v1 * q1.y;
    }
    if (j < e) {
        int r = g_csc_row[j]; float v = g_csc_val[j];
        float2 q = *(const float2*)(g_tmp + r * BB + 2 * lane);
        acc0.x += v * q.x; acc0.y += v * q.y;
    }
    float2 o = {acc0.x + acc1.x, acc0.y + acc1.y};

    if (AP_MODE) {
        float2 p = *(const float2*)(g_P + gw * BB + 2 * lane);
        o.x += LAMBDA * p.x; o.y += LAMBDA * p.y;
        *(float2*)(g_AP + gw * BB + 2 * lane) = o;
        // fused per-column dot(P, AP)
        __shared__ float sd[BB];
        if (threadIdx.x < BB) sd[threadIdx.x] = 0.f;
        __syncthreads();
        atomicAdd(&sd[2 * lane],     p.x * o.x);
        atomicAdd(&sd[2 * lane + 1], p.y * o.y);
        __syncthreads();
        if (threadIdx.x < BB) atomicAdd(&g_pAP[threadIdx.x], (double)sd[threadIdx.x]);
    } else {
        *(float2*)(g_R + gw * BB + 2 * lane) = o;   // y -> R0
    }
}

// ---------------- CG init: P0 = R0, Rs0 = sum(R0^2) per column ----------------
__global__ void k_init2() {
    int t = blockIdx.x * blockDim.x + threadIdx.x;  // 256*256 = 65536
    int c = t & 63, rstart = t >> 6;                // 1024 row-start slots
    float acc = 0.f;
    for (int row = rstart; row < NITEMS; row += 1024) {
        int i = row * BB + c;
        float r = g_R[i];
        g_P[i] = r;
        acc += r * r;
    }
    __shared__ float sd[BB];
    if (threadIdx.x < BB) sd[threadIdx.x] = 0.f;
    __syncthreads();
    atomicAdd(&sd[c], acc);
    __syncthreads();
    if (threadIdx.x < BB) atomicAdd(&g_Rs_old[threadIdx.x], (double)sd[threadIdx.x]);
}

// ---------------- CG update 1: alpha, X, R, Rs_new ----------------
__global__ void k_update1() {
    if (g_done) return;
    int t = blockIdx.x * blockDim.x + threadIdx.x;  // 65536
    int c = t & 63, rstart = t >> 6;
    float alpha = (float)(g_Rs_old[c] / (g_pAP[c] + 1e-12));
    float acc = 0.f;
    for (int row = rstart; row < NITEMS; row += 1024) {
        int i = row * BB + c;
        float p = g_P[i], ap = g_AP[i];
        g_X[i] += alpha * p;
        float r = g_R[i] - alpha * ap;
        g_R[i] = r;
        acc += r * r;
    }
    __shared__ float sd[BB];
    if (threadIdx.x < BB) sd[threadIdx.x] = 0.f;
    __syncthreads();
    atomicAdd(&sd[c], acc);
    __syncthreads();
    if (threadIdx.x < BB) atomicAdd(&g_Rs_new[threadIdx.x], (double)sd[threadIdx.x]);
}

// ---------------- CG scalar step: beta, convergence, reset accumulators ----------------
__global__ void k_scalar() {
    __shared__ double sm[BB];
    int c = threadIdx.x;                 // 64 threads
    int done = g_done;
    double rs = g_Rs_new[c];
    if (!done) {
        g_beta[c]  = (float)(rs / (g_Rs_old[c] + 1e-12));
        g_Rs_old[c] = rs;
    }
    sm[c] = rs;
    __syncthreads();
    if (c == 0 && !done) {
        double m = 0.0;
        #pragma unroll
        for (int k = 0; k < BB; k++) m = m > sm[k] ? m : sm[k];
        if (sqrt(m) < (double)TOLER) g_done = 1;
    }
    g_pAP[c] = 0.0; g_Rs_new[c] = 0.0;
}

// ---------------- CG update 2: P = R + beta * P ----------------
__global__ void k_update2() {
    if (g_done) return;
    int i = blockIdx.x * blockDim.x + threadIdx.x;  // 1048576
    int c = i & 63;
    g_P[i] = g_R[i] + g_beta[c] * g_P[i];
}

// ---------------- output: out[b][item] = X[item][b] ----------------
__global__ void k_output(float* __restrict__ out) {
    int t = blockIdx.x * blockDim.x + threadIdx.x;  // 1048576
    int b = t >> 14, item = t & 16383;
    out[t] = g_X[item * BB + b];
}

// ---------------- launch ----------------
extern "C" void kernel_launch(void* const* d_in, const int* in_sizes, int n_in,
                              void* d_out, int out_size) {
    const float* Xb   = (const float*)d_in[0];
    const int*   rows = (const int*)d_in[1];
    const int*   cols = (const int*)d_in[2];
    const float* vals = (const float*)d_in[3];
    int nnz = in_sizes[1];
    if (nnz > MAXNNZ) nnz = MAXNNZ;

    const int ELEM_BLOCKS = (NITEMS * BB) / 256;          // 4096
    const int CSR_BLOCKS  = (NUSERS * 32) / 256;          // 5000
    const int CSC_BLOCKS  = (NITEMS * 32) / 256;          // 2048

    // preprocessing: zero, histogram, scan, scatter, transpose
    k_init     <<<ELEM_BLOCKS, 256>>>();
    k_hist     <<<2048, 256>>>(rows, cols, nnz);
    k_scan     <<<1, 1024>>>(0);
    k_scan     <<<1, 1024>>>(1);
    k_scatter  <<<2048, 256>>>(rows, cols, vals, nnz);
    k_transpose<<<ELEM_BLOCKS, 256>>>(Xb);

    // RHS: y = S_mm(X_batch^T) -> g_R ;  P0 = R0 ; Rs0
    k_spmm_csr <<<CSR_BLOCKS, 256>>>(0);
    k_spmm_csc<false><<<CSC_BLOCKS, 256>>>();
    k_init2    <<<256, 256>>>();

    // 30 CG iterations
    for (int it = 0; it < MAX_ITER; it++) {
        k_spmm_csr <<<CSR_BLOCKS, 256>>>(1);
        k_spmm_csc<true><<<CSC_BLOCKS, 256>>>();
        k_update1  <<<256, 256>>>();
        k_scalar   <<<1, BB>>>();
        k_update2  <<<ELEM_BLOCKS, 256>>>();
    }

    k_output<<<ELEM_BLOCKS, 256>>>((float*)d_out);
}

// round 2
// speedup vs baseline: 1.0584x; 1.0584x over previous
#include <cuda_runtime.h>

#define NUSERS 40000
#define NITEMS 16384
#define MAXNNZ 1000000
#define BB 64
#define LAMBDA 500.0f
#define MAX_ITER 30
#define TOL2 1e-12   // TOL^2, compare against Rs (sum of squares)

// ---------------- device global scratch (no allocations allowed) ----------------
__device__ int    g_row_cnt[NUSERS];
__device__ int    g_row_ptr[NUSERS + 1];
__device__ int    g_row_off[NUSERS];
__device__ int    g_col_cnt[NITEMS];
__device__ int    g_col_ptr[NITEMS + 1];
__device__ int    g_col_off[NITEMS];
__device__ int2   g_csr[MAXNNZ];          // {col, float_bits(val)}
__device__ int2   g_csc[MAXNNZ];          // {row, float_bits(val)}
__device__ int    g_bsum[64];             // hierarchical scan block sums

__device__ float  g_tmp[NUSERS * BB];     // X @ V          (users x 64)
__device__ float  g_Xt [NITEMS * BB];     // X_batch^T      (items x 64)
__device__ float  g_X  [NITEMS * BB];     // CG solution
__device__ float  g_R  [NITEMS * BB];
__device__ float  g_P  [NITEMS * BB];
__device__ float  g_AP [NITEMS * BB];

__device__ double g_Rs_old[BB];
__device__ double g_Rs_new[BB];
__device__ double g_pAP[BB];
__device__ int    g_done;

// ---------------- init: zero everything that needs zeroing ----------------
__global__ void k_init() {
    int i = blockIdx.x * blockDim.x + threadIdx.x;   // 4096*256 = 1048576 threads
    if (i < NITEMS * BB) g_X[i] = 0.0f;
    if (i < NUSERS)      g_row_cnt[i] = 0;
    if (i < NITEMS)      g_col_cnt[i] = 0;
    if (i < BB) { g_Rs_old[i] = 0.0; g_Rs_new[i] = 0.0; g_pAP[i] = 0.0; }
    if (i == 0) g_done = 0;
}

// ---------------- histogram of rows and cols ----------------
__global__ void k_hist(const int* __restrict__ rows, const int* __restrict__ cols, int nnz) {
    for (int k = blockIdx.x * blockDim.x + threadIdx.x; k < nnz; k += gridDim.x * blockDim.x) {
        atomicAdd(&g_row_cnt[rows[k]], 1);
        atomicAdd(&g_col_cnt[cols[k]], 1);
    }
}

// ---------------- hierarchical scan ----------------
// blocks 0..39: rows (40000 = 39*1024 + 64). blocks 40..55: cols (16 * 1024).
__global__ void k_scanA() {
    __shared__ int wsum[32];
    int b = blockIdx.x;
    bool isRow = (b < 40);
    const int* cnt = isRow ? g_row_cnt : g_col_cnt;
    int* ptr = isRow ? g_row_ptr : g_col_ptr;
    int n    = isRow ? NUSERS    : NITEMS;
    int i = (isRow ? b : (b - 40)) * 1024 + threadIdx.x;
    int lane = threadIdx.x & 31, w = threadIdx.x >> 5;

    int v = (i < n) ? cnt[i] : 0;
    int x = v;
    #pragma unroll
    for (int s = 1; s < 32; s <<= 1) {
        int t = __shfl_up_sync(0xffffffffu, x, s);
        if (lane >= s) x += t;
    }
    if (lane == 31) wsum[w] = x;
    __syncthreads();
    if (w == 0) {
        int y = wsum[lane];
        #pragma unroll
        for (int s = 1; s < 32; s <<= 1) {
            int t = __shfl_up_sync(0xffffffffu, y, s);
            if (lane >= s) y += t;
        }
        wsum[lane] = y;
    }
    __syncthreads();
    int incl = x + (w ? wsum[w - 1] : 0);
    if (i < n) ptr[i] = incl - v;              // block-local exclusive
    if (threadIdx.x == 1023) g_bsum[b] = incl; // block total
}

__global__ void k_scanB() {   // 1 block, 64 threads; serial tiny scans
    int t = threadIdx.x;
    if (t == 0) {
        int s = 0;
        for (int k = 0; k < 40; k++) { int v = g_bsum[k]; g_bsum[k] = s; s += v; }
        g_row_ptr[NUSERS] = s;
    }
    if (t == 32) {
        int s = 0;
        for (int k = 40; k < 56; k++) { int v = g_bsum[k]; g_bsum[k] = s; s += v; }
        g_col_ptr[NITEMS] = s;
    }
}

__global__ void k_scanC() {
    int b = blockIdx.x;
    bool isRow = (b < 40);
    int* ptr = isRow ? g_row_ptr : g_col_ptr;
    int* off = isRow ? g_row_off : g_col_off;
    int n    = isRow ? NUSERS    : NITEMS;
    int i = (isRow ? b : (b - 40)) * 1024 + threadIdx.x;
    if (i < n) {
        int p = ptr[i] + g_bsum[b];
        ptr[i] = p;
        off[i] = p;
    }
}

// ---------------- scatter into packed CSR and CSC ----------------
__global__ void k_scatter(const int* __restrict__ rows, const int* __restrict__ cols,
                          const float* __restrict__ vals, int nnz) {
    for (int k = blockIdx.x * blockDim.x + threadIdx.x; k < nnz; k += gridDim.x * blockDim.x) {
        int r = rows[k]; int c = cols[k]; int vb = __float_as_int(vals[k]);
        int p = atomicAdd(&g_row_off[r], 1);
        g_csr[p] = make_int2(c, vb);
        int q = atomicAdd(&g_col_off[c], 1);
        g_csc[q] = make_int2(r, vb);
    }
}

// ---------------- transpose X_batch (64 x 16384) -> Xt (16384 x 64) ----------------
__global__ void k_transpose(const float* __restrict__ Xb) {
    int t = blockIdx.x * blockDim.x + threadIdx.x;   // 1048576
    int item = t >> 6, b = t & 63;
    g_Xt[t] = __ldg(&Xb[b * NITEMS + item]);
}

// ---------------- SpMM: tmp = X @ V (warp per user row) ----------------
// src: 0 -> V = g_Xt, 1 -> V = g_P.  rotate: copy Rs_new -> Rs_old (start of CG iter >0)
__global__ void k_spmm_csr(int src, int rotate) {
    if (g_done) return;
    // scalar bookkeeping for this CG iteration (runs before csc/update1 of same iter)
    if (blockIdx.x == 0 && threadIdx.x < BB) {
        if (rotate) g_Rs_old[threadIdx.x] = g_Rs_new[threadIdx.x];
        if (rotate >= 0) { g_Rs_new[threadIdx.x] = 0.0; g_pAP[threadIdx.x] = 0.0; }
    }
    const float* __restrict__ V = src ? g_P : g_Xt;
    int gw   = (blockIdx.x * blockDim.x + threadIdx.x) >> 5;  // 40000 warps exactly
    int lane = threadIdx.x & 31;
    int s = g_row_ptr[gw], e = g_row_ptr[gw + 1];
    float2 a0 = {0.f,0.f}, a1 = {0.f,0.f}, a2 = {0.f,0.f}, a3 = {0.f,0.f};
    int j = s;
    for (; j + 3 < e; j += 4) {
        int2 p0 = g_csr[j], p1 = g_csr[j+1], p2 = g_csr[j+2], p3 = g_csr[j+3];
        float2 q0 = *(const float2*)(V + p0.x * BB + 2 * lane);
        float2 q1 = *(const float2*)(V + p1.x * BB + 2 * lane);
        float2 q2 = *(const float2*)(V + p2.x * BB + 2 * lane);
        float2 q3 = *(const float2*)(V + p3.x * BB + 2 * lane);
        float v0 = __int_as_float(p0.y), v1 = __int_as_float(p1.y);
        float v2 = __int_as_float(p2.y), v3 = __int_as_float(p3.y);
        a0.x += v0*q0.x; a0.y += v0*q0.y;
        a1.x += v1*q1.x; a1.y += v1*q1.y;
        a2.x += v2*q2.x; a2.y += v2*q2.y;
        a3.x += v3*q3.x; a3.y += v3*q3.y;
    }
    for (; j < e; j++) {
        int2 p = g_csr[j];
        float2 q = *(const float2*)(V + p.x * BB + 2 * lane);
        float v = __int_as_float(p.y);
        a0.x += v*q.x; a0.y += v*q.y;
    }
    float2 o = { (a0.x + a1.x) + (a2.x + a3.x), (a0.y + a1.y) + (a2.y + a3.y) };
    *(float2*)(g_tmp + gw * BB + 2 * lane) = o;
}

// ---------------- SpMM: out = X^T @ tmp  (+ lambda*P, + dot(P,AP)) ----------------
// AP_MODE=false: RHS pass -> writes R0 and P0, accumulates Rs0 into Rs_old.
template <bool AP_MODE>
__global__ void k_spmm_csc() {
    if (g_done) return;
    int gw   = (blockIdx.x * blockDim.x + threadIdx.x) >> 5;  // 16384 warps exactly
    int lane = threadIdx.x & 31;
    int s = g_col_ptr[gw], e = g_col_ptr[gw + 1];
    float2 a0 = {0.f,0.f}, a1 = {0.f,0.f}, a2 = {0.f,0.f}, a3 = {0.f,0.f};
    int j = s;
    for (; j + 3 < e; j += 4) {
        int2 p0 = g_csc[j], p1 = g_csc[j+1], p2 = g_csc[j+2], p3 = g_csc[j+3];
        float2 q0 = *(const float2*)(g_tmp + p0.x * BB + 2 * lane);
        float2 q1 = *(const float2*)(g_tmp + p1.x * BB + 2 * lane);
        float2 q2 = *(const float2*)(g_tmp + p2.x * BB + 2 * lane);
        float2 q3 = *(const float2*)(g_tmp + p3.x * BB + 2 * lane);
        float v0 = __int_as_float(p0.y), v1 = __int_as_float(p1.y);
        float v2 = __int_as_float(p2.y), v3 = __int_as_float(p3.y);
        a0.x += v0*q0.x; a0.y += v0*q0.y;
        a1.x += v1*q1.x; a1.y += v1*q1.y;
        a2.x += v2*q2.x; a2.y += v2*q2.y;
        a3.x += v3*q3.x; a3.y += v3*q3.y;
    }
    for (; j < e; j++) {
        int2 p = g_csc[j];
        float2 q = *(const float2*)(g_tmp + p.x * BB + 2 * lane);
        float v = __int_as_float(p.y);
        a0.x += v*q.x; a0.y += v*q.y;
    }
    float2 o = { (a0.x + a1.x) + (a2.x + a3.x), (a0.y + a1.y) + (a2.y + a3.y) };

    __shared__ float sd[BB];
    if (threadIdx.x < BB) sd[threadIdx.x] = 0.f;
    __syncthreads();

    if (AP_MODE) {
        float2 p = *(const float2*)(g_P + gw * BB + 2 * lane);
        o.x += LAMBDA * p.x; o.y += LAMBDA * p.y;
        *(float2*)(g_AP + gw * BB + 2 * lane) = o;
        atomicAdd(&sd[2 * lane],     p.x * o.x);
        atomicAdd(&sd[2 * lane + 1], p.y * o.y);
        __syncthreads();
        if (threadIdx.x < BB) atomicAdd(&g_pAP[threadIdx.x], (double)sd[threadIdx.x]);
    } else {
        // y -> R0, P0 = R0, Rs0 accumulation
        *(float2*)(g_R + gw * BB + 2 * lane) = o;
        *(float2*)(g_P + gw * BB + 2 * lane) = o;
        atomicAdd(&sd[2 * lane],     o.x * o.x);
        atomicAdd(&sd[2 * lane + 1], o.y * o.y);
        __syncthreads();
        if (threadIdx.x < BB) atomicAdd(&g_Rs_old[threadIdx.x], (double)sd[threadIdx.x]);
    }
}

// ---------------- CG update 1: alpha, X, R, Rs_new ----------------
__global__ void k_update1() {
    if (g_done) return;
    __shared__ float s_alpha[BB];
    __shared__ float sd[BB];
    if (threadIdx.x < BB) {
        s_alpha[threadIdx.x] =
            (float)g_Rs_old[threadIdx.x] / ((float)g_pAP[threadIdx.x] + 1e-12f);
        sd[threadIdx.x] = 0.f;
    }
    __syncthreads();
    int t = blockIdx.x * blockDim.x + threadIdx.x;  // 65536
    int c = t & 63, rstart = t >> 6;
    float alpha = s_alpha[c];
    float acc = 0.f;
    for (int row = rstart; row < NITEMS; row += 1024) {
        int i = row * BB + c;
        float p = g_P[i], ap = g_AP[i];
        g_X[i] += alpha * p;
        float r = g_R[i] - alpha * ap;
        g_R[i] = r;
        acc += r * r;
    }
    atomicAdd(&sd[c], acc);
    __syncthreads();
    if (threadIdx.x < BB) atomicAdd(&g_Rs_new[threadIdx.x], (double)sd[threadIdx.x]);
}

// ---------------- CG update 2 (+fused scalar step): P = R + beta * P ----------------
__global__ void k_update2() {
    if (g_done) return;
    __shared__ float s_beta[BB];
    __shared__ int s_ok;
    if (threadIdx.x == 0) s_ok = 1;
    __syncthreads();
    if (threadIdx.x < BB) {
        double rsn = g_Rs_new[threadIdx.x];
        s_beta[threadIdx.x] = (float)rsn / ((float)g_Rs_old[threadIdx.x] + 1e-12f);
        if (blockIdx.x == 0 && rsn >= TOL2) s_ok = 0;
    }
    __syncthreads();
    int i = blockIdx.x * blockDim.x + threadIdx.x;  // 1048576
    int c = i & 63;
    g_P[i] = g_R[i] + s_beta[c] * g_P[i];
    if (blockIdx.x == 0 && threadIdx.x == 0 && s_ok) g_done = 1;
}

// ---------------- output: out[b][item] = X[item][b] ----------------
__global__ void k_output(float* __restrict__ out) {
    int t = blockIdx.x * blockDim.x + threadIdx.x;  // 1048576
    int b = t >> 14, item = t & 16383;
    out[t] = g_X[item * BB + b];
}

// ---------------- launch ----------------
extern "C" void kernel_launch(void* const* d_in, const int* in_sizes, int n_in,
                              void* d_out, int out_size) {
    const float* Xb   = (const float*)d_in[0];
    const int*   rows = (const int*)d_in[1];
    const int*   cols = (const int*)d_in[2];
    const float* vals = (const float*)d_in[3];
    int nnz = in_sizes[1];
    if (nnz > MAXNNZ) nnz = MAXNNZ;

    const int ELEM_BLOCKS = (NITEMS * BB) / 256;          // 4096
    const int CSR_BLOCKS  = (NUSERS * 32) / 256;          // 5000
    const int CSC_BLOCKS  = (NITEMS * 32) / 256;          // 2048

    // preprocessing
    k_init     <<<ELEM_BLOCKS, 256>>>();
    k_hist     <<<2048, 256>>>(rows, cols, nnz);
    k_scanA    <<<56, 1024>>>();
    k_scanB    <<<1, 64>>>();
    k_scanC    <<<56, 1024>>>();
    k_scatter  <<<2048, 256>>>(rows, cols, vals, nnz);
    k_transpose<<<ELEM_BLOCKS, 256>>>(Xb);

    // RHS: y = S_mm(X_batch^T) -> R0, P0, Rs0 (fused)
    k_spmm_csr <<<CSR_BLOCKS, 256>>>(0, -1);   // rotate<0: no scalar bookkeeping
    k_spmm_csc<false><<<CSC_BLOCKS, 256>>>();

    // 30 CG iterations (4 kernels each)
    for (int it = 0; it < MAX_ITER; it++) {
        k_spmm_csr <<<CSR_BLOCKS, 256>>>(1, it > 0 ? 1 : 0);
        k_spmm_csc<true><<<CSC_BLOCKS, 256>>>();
        k_update1  <<<256, 256>>>();
        k_update2  <<<ELEM_BLOCKS, 256>>>();
    }

    k_output<<<ELEM_BLOCKS, 256>>>((float*)d_out);
}

// round 3
// speedup vs baseline: 1.1397x; 1.0768x over previous
#include <cuda_runtime.h>

#define NUSERS 40000
#define NITEMS 16384
#define MAXNNZ 1000000
#define BB 64
#define LAMBDA 500.0f
#define MAX_ITER 30
#define TOL2 1e-12   // TOL^2, compare against Rs (sum of squares)

// ---------------- device global scratch (no allocations allowed) ----------------
__device__ int    g_row_cnt[NUSERS];
__device__ int    g_row_ptr[NUSERS + 1];
__device__ int    g_row_off[NUSERS];
__device__ int    g_col_cnt[NITEMS];
__device__ int    g_col_ptr[NITEMS + 1];
__device__ int    g_col_off[NITEMS];
__device__ int2   g_csr[MAXNNZ];          // {col, float_bits(val)}
__device__ int2   g_csc[MAXNNZ];          // {row, float_bits(val)}
__device__ int    g_bsum[64];             // hierarchical scan block sums

__device__ float  g_tmp[NUSERS * BB];     // X @ V          (users x 64)
__device__ float  g_Xt [NITEMS * BB];     // X_batch^T      (items x 64)
__device__ float  g_X  [NITEMS * BB];     // CG solution
__device__ float  g_R  [NITEMS * BB];
__device__ float  g_P  [NITEMS * BB];
__device__ float  g_AP [NITEMS * BB];

__device__ double g_Rs_old[BB];
__device__ double g_Rs_new[BB];
__device__ double g_pAP[BB];
__device__ int    g_done;

// ---------------- grid-wide barrier (sense via generation counter) ----------------
// Leaves g_bar_cnt == 0 after every use -> safe across graph replays.
__device__ unsigned g_bar_cnt;
__device__ unsigned g_bar_gen;

__device__ __forceinline__ void grid_barrier(unsigned nblocks) {
    __syncthreads();
    if (threadIdx.x == 0) {
        unsigned gen = *(volatile unsigned*)&g_bar_gen;
        __threadfence();
        unsigned old = atomicAdd(&g_bar_cnt, 1u);
        if (old == nblocks - 1u) {
            g_bar_cnt = 0u;
            __threadfence();
            atomicAdd(&g_bar_gen, 1u);
        } else {
            while (*(volatile unsigned*)&g_bar_gen == gen) { }
        }
        __threadfence();
    }
    __syncthreads();
}

// ---------------- init: zero counters/scalars, X=0, and transpose X_batch ----------------
__global__ void k_init(const float* __restrict__ Xb) {
    int i = blockIdx.x * blockDim.x + threadIdx.x;   // 4096*256 = 1048576 threads
    if (i < NITEMS * BB) {
        g_X[i] = 0.0f;
        int item = i >> 6, b = i & 63;
        g_Xt[i] = __ldg(&Xb[b * NITEMS + item]);
    }
    if (i < NUSERS)      g_row_cnt[i] = 0;
    if (i < NITEMS)      g_col_cnt[i] = 0;
    if (i < BB) { g_Rs_old[i] = 0.0; g_Rs_new[i] = 0.0; g_pAP[i] = 0.0; }
    if (i == 0) g_done = 0;
}

// ---------------- histogram of rows and cols ----------------
__global__ void k_hist(const int* __restrict__ rows, const int* __restrict__ cols, int nnz) {
    for (int k = blockIdx.x * blockDim.x + threadIdx.x; k < nnz; k += gridDim.x * blockDim.x) {
        atomicAdd(&g_row_cnt[rows[k]], 1);
        atomicAdd(&g_col_cnt[cols[k]], 1);
    }
}

// ---------------- fused hierarchical scan: one kernel, 56 resident blocks ----------------
// blocks 0..39: rows (40000 = 39*1024 + 64). blocks 40..55: cols (16 * 1024).
__global__ void k_scan() {
    __shared__ int wsum[32];
    int b = blockIdx.x;
    bool isRow = (b < 40);
    const int* cnt = isRow ? g_row_cnt : g_col_cnt;
    int* ptr = isRow ? g_row_ptr : g_col_ptr;
    int* off = isRow ? g_row_off : g_col_off;
    int n    = isRow ? NUSERS    : NITEMS;
    int i = (isRow ? b : (b - 40)) * 1024 + threadIdx.x;
    int lane = threadIdx.x & 31, w = threadIdx.x >> 5;

    // phase A: block-local exclusive scan
    int v = (i < n) ? cnt[i] : 0;
    int x = v;
    #pragma unroll
    for (int s = 1; s < 32; s <<= 1) {
        int t = __shfl_up_sync(0xffffffffu, x, s);
        if (lane >= s) x += t;
    }
    if (lane == 31) wsum[w] = x;
    __syncthreads();
    if (w == 0) {
        int y = wsum[lane];
        #pragma unroll
        for (int s = 1; s < 32; s <<= 1) {
            int t = __shfl_up_sync(0xffffffffu, y, s);
            if (lane >= s) y += t;
        }
        wsum[lane] = y;
    }
    __syncthreads();
    int incl = x + (w ? wsum[w - 1] : 0);
    int loc_excl = incl - v;
    if (threadIdx.x == 1023) g_bsum[b] = incl;

    grid_barrier(56);

    // phase B: tiny serial scans of block sums (parallel across two blocks)
    if (b == 0 && threadIdx.x == 0) {
        int s = 0;
        for (int k = 0; k < 40; k++) { int t = g_bsum[k]; g_bsum[k] = s; s += t; }
        g_row_ptr[NUSERS] = s;
    }
    if (b == 1 && threadIdx.x == 0) {
        int s = 0;
        for (int k = 40; k < 56; k++) { int t = g_bsum[k]; g_bsum[k] = s; s += t; }
        g_col_ptr[NITEMS] = s;
    }

    grid_barrier(56);

    // phase C: add block offsets
    if (i < n) {
        int p = loc_excl + g_bsum[b];
        ptr[i] = p;
        off[i] = p;
    }
}

// ---------------- scatter into packed CSR and CSC ----------------
__global__ void k_scatter(const int* __restrict__ rows, const int* __restrict__ cols,
                          const float* __restrict__ vals, int nnz) {
    for (int k = blockIdx.x * blockDim.x + threadIdx.x; k < nnz; k += gridDim.x * blockDim.x) {
        int r = rows[k]; int c = cols[k]; int vb = __float_as_int(vals[k]);
        int p = atomicAdd(&g_row_off[r], 1);
        g_csr[p] = make_int2(c, vb);
        int q = atomicAdd(&g_col_off[c], 1);
        g_csc[q] = make_int2(r, vb);
    }
}

// ---------------- SpMM: tmp = X @ V (warp per user row) ----------------
// src: 0 -> V = g_Xt, 1 -> V = g_P.  rotate: 1 = Rs_old <- Rs_new; >=0 resets accumulators
__global__ void k_spmm_csr(int src, int rotate) {
    if (g_done) return;
    if (blockIdx.x == 0 && threadIdx.x < BB) {
        if (rotate > 0) g_Rs_old[threadIdx.x] = g_Rs_new[threadIdx.x];
        if (rotate >= 0) { g_Rs_new[threadIdx.x] = 0.0; g_pAP[threadIdx.x] = 0.0; }
    }
    const float* __restrict__ V = src ? g_P : g_Xt;
    int gw   = (blockIdx.x * blockDim.x + threadIdx.x) >> 5;  // 40000 warps exactly
    int lane = threadIdx.x & 31;
    int s = g_row_ptr[gw], e = g_row_ptr[gw + 1];
    float2 a0 = {0.f,0.f}, a1 = {0.f,0.f}, a2 = {0.f,0.f}, a3 = {0.f,0.f};
    int j = s;
    for (; j + 3 < e; j += 4) {
        int2 p0 = g_csr[j], p1 = g_csr[j+1], p2 = g_csr[j+2], p3 = g_csr[j+3];
        float2 q0 = *(const float2*)(V + p0.x * BB + 2 * lane);
        float2 q1 = *(const float2*)(V + p1.x * BB + 2 * lane);
        float2 q2 = *(const float2*)(V + p2.x * BB + 2 * lane);
        float2 q3 = *(const float2*)(V + p3.x * BB + 2 * lane);
        float v0 = __int_as_float(p0.y), v1 = __int_as_float(p1.y);
        float v2 = __int_as_float(p2.y), v3 = __int_as_float(p3.y);
        a0.x += v0*q0.x; a0.y += v0*q0.y;
        a1.x += v1*q1.x; a1.y += v1*q1.y;
        a2.x += v2*q2.x; a2.y += v2*q2.y;
        a3.x += v3*q3.x; a3.y += v3*q3.y;
    }
    for (; j < e; j++) {
        int2 p = g_csr[j];
        float2 q = *(const float2*)(V + p.x * BB + 2 * lane);
        float v = __int_as_float(p.y);
        a0.x += v*q.x; a0.y += v*q.y;
    }
    float2 o = { (a0.x + a1.x) + (a2.x + a3.x), (a0.y + a1.y) + (a2.y + a3.y) };
    *(float2*)(g_tmp + gw * BB + 2 * lane) = o;
}

// ---------------- SpMM: out = X^T @ tmp  (+ lambda*P, + dot(P,AP)) ----------------
// AP_MODE=false: RHS pass -> writes R0 and P0, accumulates Rs0 into Rs_old.
template <bool AP_MODE>
__global__ void k_spmm_csc() {
    if (g_done) return;
    int gw   = (blockIdx.x * blockDim.x + threadIdx.x) >> 5;  // 16384 warps exactly
    int lane = threadIdx.x & 31;
    int s = g_col_ptr[gw], e = g_col_ptr[gw + 1];
    float2 a0 = {0.f,0.f}, a1 = {0.f,0.f}, a2 = {0.f,0.f}, a3 = {0.f,0.f};
    int j = s;
    for (; j + 3 < e; j += 4) {
        int2 p0 = g_csc[j], p1 = g_csc[j+1], p2 = g_csc[j+2], p3 = g_csc[j+3];
        float2 q0 = *(const float2*)(g_tmp + p0.x * BB + 2 * lane);
        float2 q1 = *(const float2*)(g_tmp + p1.x * BB + 2 * lane);
        float2 q2 = *(const float2*)(g_tmp + p2.x * BB + 2 * lane);
        float2 q3 = *(const float2*)(g_tmp + p3.x * BB + 2 * lane);
        float v0 = __int_as_float(p0.y), v1 = __int_as_float(p1.y);
        float v2 = __int_as_float(p2.y), v3 = __int_as_float(p3.y);
        a0.x += v0*q0.x; a0.y += v0*q0.y;
        a1.x += v1*q1.x; a1.y += v1*q1.y;
        a2.x += v2*q2.x; a2.y += v2*q2.y;
        a3.x += v3*q3.x; a3.y += v3*q3.y;
    }
    for (; j < e; j++) {
        int2 p = g_csc[j];
        float2 q = *(const float2*)(g_tmp + p.x * BB + 2 * lane);
        float v = __int_as_float(p.y);
        a0.x += v*q.x; a0.y += v*q.y;
    }
    float2 o = { (a0.x + a1.x) + (a2.x + a3.x), (a0.y + a1.y) + (a2.y + a3.y) };

    __shared__ float sd[BB];
    if (threadIdx.x < BB) sd[threadIdx.x] = 0.f;
    __syncthreads();

    if (AP_MODE) {
        float2 p = *(const float2*)(g_P + gw * BB + 2 * lane);
        o.x += LAMBDA * p.x; o.y += LAMBDA * p.y;
        *(float2*)(g_AP + gw * BB + 2 * lane) = o;
        atomicAdd(&sd[2 * lane],     p.x * o.x);
        atomicAdd(&sd[2 * lane + 1], p.y * o.y);
        __syncthreads();
        if (threadIdx.x < BB) atomicAdd(&g_pAP[threadIdx.x], (double)sd[threadIdx.x]);
    } else {
        *(float2*)(g_R + gw * BB + 2 * lane) = o;
        *(float2*)(g_P + gw * BB + 2 * lane) = o;
        atomicAdd(&sd[2 * lane],     o.x * o.x);
        atomicAdd(&sd[2 * lane + 1], o.y * o.y);
        __syncthreads();
        if (threadIdx.x < BB) atomicAdd(&g_Rs_old[threadIdx.x], (double)sd[threadIdx.x]);
    }
}

// ---------------- fused CG vector update: alpha,X,R,Rs_new | barrier | beta,P ----------------
// 256 blocks x 256 threads, all resident. Each thread owns one batch column c
// and ROWS_PT=16 rows; r,p cached in registers across the barrier.
#define UPD_BLOCKS 256
#define ROWS_PT    (NITEMS / 1024)   // 16

__global__ void __launch_bounds__(256, 2) k_update() {
    if (g_done) return;
    __shared__ float s_alpha[BB];
    __shared__ float sd[BB];
    __shared__ int   s_ok;
    if (threadIdx.x < BB) {
        s_alpha[threadIdx.x] =
            (float)g_Rs_old[threadIdx.x] / ((float)g_pAP[threadIdx.x] + 1e-12f);
        sd[threadIdx.x] = 0.f;
    }
    if (threadIdx.x == 0) s_ok = 1;
    __syncthreads();

    int t = blockIdx.x * blockDim.x + threadIdx.x;  // 65536
    int c = t & 63, rstart = t >> 6;                // 1024 row-start slots
    float alpha = s_alpha[c];

    float rc[ROWS_PT], pc[ROWS_PT];
    float acc = 0.f;
    #pragma unroll
    for (int k = 0; k < ROWS_PT; k++) {
        int i = (rstart + k * 1024) * BB + c;
        float p = g_P[i], ap = g_AP[i];
        g_X[i] += alpha * p;
        float r = g_R[i] - alpha * ap;
        g_R[i] = r;
        rc[k] = r; pc[k] = p;
        acc += r * r;
    }
    atomicAdd(&sd[c], acc);
    __syncthreads();
    if (threadIdx.x < BB) atomicAdd(&g_Rs_new[threadIdx.x], (double)sd[threadIdx.x]);

    grid_barrier(UPD_BLOCKS);

    // phase 2: beta + P update from registers
    __shared__ float s_beta[BB];
    if (threadIdx.x < BB) {
        double rsn = g_Rs_new[threadIdx.x];
        s_beta[threadIdx.x] = (float)rsn / ((float)g_Rs_old[threadIdx.x] + 1e-12f);
        if (rsn >= TOL2) s_ok = 0;
    }
    __syncthreads();
    float beta = s_beta[c];
    #pragma unroll
    for (int k = 0; k < ROWS_PT; k++) {
        int i = (rstart + k * 1024) * BB + c;
        g_P[i] = rc[k] + beta * pc[k];
    }
    if (blockIdx.x == 0 && threadIdx.x == 0 && s_ok) g_done = 1;
}

// ---------------- output: out[b][item] = X[item][b] ----------------
__global__ void k_output(float* __restrict__ out) {
    int t = blockIdx.x * blockDim.x + threadIdx.x;  // 1048576
    int b = t >> 14, item = t & 16383;
    out[t] = g_X[item * BB + b];
}

// ---------------- launch ----------------
extern "C" void kernel_launch(void* const* d_in, const int* in_sizes, int n_in,
                              void* d_out, int out_size) {
    const float* Xb   = (const float*)d_in[0];
    const int*   rows = (const int*)d_in[1];
    const int*   cols = (const int*)d_in[2];
    const float* vals = (const float*)d_in[3];
    int nnz = in_sizes[1];
    if (nnz > MAXNNZ) nnz = MAXNNZ;

    const int ELEM_BLOCKS = (NITEMS * BB) / 256;          // 4096
    const int CSR_BLOCKS  = (NUSERS * 32) / 256;          // 5000
    const int CSC_BLOCKS  = (NITEMS * 32) / 256;          // 2048

    // preprocessing (4 launches)
    k_init   <<<ELEM_BLOCKS, 256>>>(Xb);
    k_hist   <<<2048, 256>>>(rows, cols, nnz);
    k_scan   <<<56, 1024>>>();
    k_scatter<<<2048, 256>>>(rows, cols, vals, nnz);

    // RHS: y = S_mm(X_batch^T) -> R0, P0, Rs0 (fused)
    k_spmm_csr <<<CSR_BLOCKS, 256>>>(0, -1);
    k_spmm_csc<false><<<CSC_BLOCKS, 256>>>();

    // 30 CG iterations (3 kernels each)
    for (int it = 0; it < MAX_ITER; it++) {
        k_spmm_csr <<<CSR_BLOCKS, 256>>>(1, it > 0 ? 1 : 0);
        k_spmm_csc<true><<<CSC_BLOCKS, 256>>>();
        k_update   <<<UPD_BLOCKS, 256>>>();
    }

    k_output<<<ELEM_BLOCKS, 256>>>((float*)d_out);
}

// round 4
// speedup vs baseline: 1.2318x; 1.0808x over previous
#include <cuda_runtime.h>

#define NUSERS 40000
#define NITEMS 16384
#define MAXNNZ 1000000
#define BB 64
#define LAMBDA 500.0f
#define MAX_ITER 30
#define TOL2 1e-12   // TOL^2, compare vs Rs (sum of squares)

#define PBLOCKS 888                   // 148 SMs x 6 blocks (forced by launch_bounds)
#define PTHREADS (PBLOCKS * 256)      // 227328
#define PWARPS   (PTHREADS / 32)      // 7104
#define NELEM    (NITEMS * BB)        // 1048576

// ---------------- device global scratch ----------------
__device__ int    g_row_cnt[NUSERS];
__device__ int    g_row_ptr[NUSERS + 1];
__device__ int    g_row_off[NUSERS];
__device__ int    g_col_cnt[NITEMS];
__device__ int    g_col_ptr[NITEMS + 1];
__device__ int    g_col_off[NITEMS];
__device__ int2   g_csr[MAXNNZ];          // {col, float_bits(val)}
__device__ int2   g_csc[MAXNNZ];          // {row, float_bits(val)}
__device__ int    g_bsum[64];

__device__ float  g_tmp[NUSERS * BB];
__device__ float  g_Xt [NELEM];
__device__ float  g_X  [NELEM];
__device__ float  g_R  [NELEM];
__device__ float  g_P  [NELEM];
__device__ float  g_AP [NELEM];

__device__ double g_RsA[BB];   // Rs_old
__device__ double g_RsB[BB];   // Rs_new
__device__ double g_pAP[BB];
__device__ int    g_done;

// ---------------- grid-wide barrier (sense via generation counter) ----------------
__device__ unsigned g_bar_cnt;
__device__ unsigned g_bar_gen;

__device__ __forceinline__ void grid_barrier(unsigned nblocks) {
    __syncthreads();
    if (threadIdx.x == 0) {
        unsigned gen = *(volatile unsigned*)&g_bar_gen;
        __threadfence();
        if (atomicAdd(&g_bar_cnt, 1u) == nblocks - 1u) {
            g_bar_cnt = 0u;
            __threadfence();
            atomicAdd(&g_bar_gen, 1u);
        } else {
            while (*(volatile unsigned*)&g_bar_gen == gen) { }
        }
        __threadfence();
    }
    __syncthreads();
}

// ---------------- gather of one sparse row into a warp-held float2 ----------------
__device__ __forceinline__ float2 row_gather(const int2* __restrict__ idx,
                                             const float* __restrict__ V,
                                             int s, int e, int lane) {
    float2 a0 = {0.f,0.f}, a1 = {0.f,0.f}, a2 = {0.f,0.f}, a3 = {0.f,0.f};
    int j = s;
    for (; j + 3 < e; j += 4) {
        int2 p0 = __ldcs(idx + j),     p1 = __ldcs(idx + j + 1);
        int2 p2 = __ldcs(idx + j + 2), p3 = __ldcs(idx + j + 3);
        float2 q0 = *(const float2*)(V + p0.x * BB + 2 * lane);
        float2 q1 = *(const float2*)(V + p1.x * BB + 2 * lane);
        float2 q2 = *(const float2*)(V + p2.x * BB + 2 * lane);
        float2 q3 = *(const float2*)(V + p3.x * BB + 2 * lane);
        float v0 = __int_as_float(p0.y), v1 = __int_as_float(p1.y);
        float v2 = __int_as_float(p2.y), v3 = __int_as_float(p3.y);
        a0.x += v0*q0.x; a0.y += v0*q0.y;
        a1.x += v1*q1.x; a1.y += v1*q1.y;
        a2.x += v2*q2.x; a2.y += v2*q2.y;
        a3.x += v3*q3.x; a3.y += v3*q3.y;
    }
    for (; j < e; j++) {
        int2 p = __ldcs(idx + j);
        float2 q = *(const float2*)(V + p.x * BB + 2 * lane);
        float v = __int_as_float(p.y);
        a0.x += v*q.x; a0.y += v*q.y;
    }
    return make_float2((a0.x + a1.x) + (a2.x + a3.x),
                       (a0.y + a1.y) + (a2.y + a3.y));
}

// ---------------- init: zero counters/scalars, X=0, transpose X_batch ----------------
__global__ void k_init(const float* __restrict__ Xb) {
    int i = blockIdx.x * blockDim.x + threadIdx.x;   // 1048576 threads
    if (i < NELEM) {
        g_X[i] = 0.0f;
        int item = i >> 6, b = i & 63;
        g_Xt[i] = __ldg(&Xb[b * NITEMS + item]);
    }
    if (i < NUSERS) g_row_cnt[i] = 0;
    if (i < NITEMS) g_col_cnt[i] = 0;
    if (i < BB) { g_RsA[i] = 0.0; g_RsB[i] = 0.0; g_pAP[i] = 0.0; }
    if (i == 0) g_done = 0;
}

// ---------------- histogram ----------------
__global__ void k_hist(const int* __restrict__ rows, const int* __restrict__ cols, int nnz) {
    int k = blockIdx.x * blockDim.x + threadIdx.x;   // 1 nnz per thread
    if (k < nnz) {
        atomicAdd(&g_row_cnt[__ldcs(rows + k)], 1);
        atomicAdd(&g_col_cnt[__ldcs(cols + k)], 1);
    }
}

// ---------------- fused hierarchical scan (56 resident blocks) ----------------
__global__ void k_scan() {
    __shared__ int wsum[32];
    int b = blockIdx.x;
    bool isRow = (b < 40);
    const int* cnt = isRow ? g_row_cnt : g_col_cnt;
    int* ptr = isRow ? g_row_ptr : g_col_ptr;
    int* off = isRow ? g_row_off : g_col_off;
    int n    = isRow ? NUSERS    : NITEMS;
    int i = (isRow ? b : (b - 40)) * 1024 + threadIdx.x;
    int lane = threadIdx.x & 31, w = threadIdx.x >> 5;

    int v = (i < n) ? cnt[i] : 0;
    int x = v;
    #pragma unroll
    for (int s = 1; s < 32; s <<= 1) {
        int t = __shfl_up_sync(0xffffffffu, x, s);
        if (lane >= s) x += t;
    }
    if (lane == 31) wsum[w] = x;
    __syncthreads();
    if (w == 0) {
        int y = wsum[lane];
        #pragma unroll
        for (int s = 1; s < 32; s <<= 1) {
            int t = __shfl_up_sync(0xffffffffu, y, s);
            if (lane >= s) y += t;
        }
        wsum[lane] = y;
    }
    __syncthreads();
    int incl = x + (w ? wsum[w - 1] : 0);
    int loc_excl = incl - v;
    if (threadIdx.x == 1023) g_bsum[b] = incl;

    grid_barrier(56);

    if (b == 0 && threadIdx.x == 0) {
        int s = 0;
        for (int k = 0; k < 40; k++) { int t = g_bsum[k]; g_bsum[k] = s; s += t; }
        g_row_ptr[NUSERS] = s;
    }
    if (b == 1 && threadIdx.x == 0) {
        int s = 0;
        for (int k = 40; k < 56; k++) { int t = g_bsum[k]; g_bsum[k] = s; s += t; }
        g_col_ptr[NITEMS] = s;
    }

    grid_barrier(56);

    if (i < n) {
        int p = loc_excl + g_bsum[b];
        ptr[i] = p;
        off[i] = p;
    }
}

// ---------------- scatter: 1 nnz per thread (max ILP) ----------------
__global__ void k_scatter(const int* __restrict__ rows, const int* __restrict__ cols,
                          const float* __restrict__ vals, int nnz) {
    int k = blockIdx.x * blockDim.x + threadIdx.x;
    if (k < nnz) {
        int r = __ldcs(rows + k); int c = __ldcs(cols + k);
        int vb = __float_as_int(__ldcs(vals + k));
        int p = atomicAdd(&g_row_off[r], 1);
        g_csr[p] = make_int2(c, vb);
        int q = atomicAdd(&g_col_off[c], 1);
        g_csc[q] = make_int2(r, vb);
    }
}

// ---------------- standalone RHS csr pass: tmp = X @ Xt (full-width grid) ----------------
__global__ void k_spmm_csr_rhs() {
    int gw   = (blockIdx.x * blockDim.x + threadIdx.x) >> 5;  // 40000 warps
    int lane = threadIdx.x & 31;
    float2 o = row_gather(g_csr, g_Xt, g_row_ptr[gw], g_row_ptr[gw + 1], lane);
    *(float2*)(g_tmp + gw * BB + 2 * lane) = o;
}

// ---------------- persistent CG mega-kernel ----------------
__global__ void __launch_bounds__(256, 6) k_cg() {
    __shared__ float sd[BB];
    __shared__ float s_a[BB];        // alpha, then beta
    __shared__ float s_rsold[BB];

    int tid  = threadIdx.x;
    int gt   = blockIdx.x * 256 + tid;
    int gw   = gt >> 5;
    int lane = tid & 31;
    int c0   = 2 * lane;
    int c    = tid & 63;   // PTHREADS stride is a multiple of 64 -> column fixed per thread

    // ===== RHS csc phase: R0 = P0 = X^T tmp ; RsA = sum(R0^2) =====
    {
        if (tid < BB) sd[tid] = 0.f;
        __syncthreads();
        float accx = 0.f, accy = 0.f;
        for (int row = gw; row < NITEMS; row += PWARPS) {
            float2 o = row_gather(g_csc, g_tmp, g_col_ptr[row], g_col_ptr[row + 1], lane);
            *(float2*)(g_R + row * BB + c0) = o;
            *(float2*)(g_P + row * BB + c0) = o;
            accx += o.x * o.x; accy += o.y * o.y;
        }
        atomicAdd(&sd[c0], accx); atomicAdd(&sd[c0 + 1], accy);
        __syncthreads();
        if (tid < BB) atomicAdd(&g_RsA[tid], (double)sd[tid]);
    }
    grid_barrier(PBLOCKS);

    // ===== 30 CG iterations =====
    for (int it = 0; it < MAX_ITER; it++) {
        // ---- csr phase: tmp = X @ P ; block0 zeroes RsB for this iter
        if (blockIdx.x == 0 && tid < BB) g_RsB[tid] = 0.0;
        for (int row = gw; row < NUSERS; row += PWARPS) {
            float2 o = row_gather(g_csr, g_P, g_row_ptr[row], g_row_ptr[row + 1], lane);
            *(float2*)(g_tmp + row * BB + c0) = o;
        }
        grid_barrier(PBLOCKS);

        // ---- csc phase: AP = X^T tmp + lambda P ; pAP += P.AP
        {
            if (tid < BB) sd[tid] = 0.f;
            __syncthreads();
            float accx = 0.f, accy = 0.f;
            for (int row = gw; row < NITEMS; row += PWARPS) {
                float2 o = row_gather(g_csc, g_tmp, g_col_ptr[row], g_col_ptr[row + 1], lane);
                float2 p = *(const float2*)(g_P + row * BB + c0);
                o.x += LAMBDA * p.x; o.y += LAMBDA * p.y;
                *(float2*)(g_AP + row * BB + c0) = o;
                accx += p.x * o.x; accy += p.y * o.y;
            }
            atomicAdd(&sd[c0], accx); atomicAdd(&sd[c0 + 1], accy);
            __syncthreads();
            if (tid < BB) atomicAdd(&g_pAP[tid], (double)sd[tid]);
        }
        grid_barrier(PBLOCKS);

        // ---- update1: alpha; X += aP; R -= a AP; RsB = sum(R^2). Cache r,p in regs.
        float rc[5], pc[5];
        {
            if (tid < BB) {
                float rso = (float)g_RsA[tid];
                s_a[tid] = rso / ((float)g_pAP[tid] + 1e-12f);
                s_rsold[tid] = rso;
                sd[tid] = 0.f;
            }
            __syncthreads();
            float alpha = s_a[c];
            float acc = 0.f;
            #pragma unroll
            for (int k = 0; k < 5; k++) {
                int i = gt + k * PTHREADS;
                if (i < NELEM) {
                    float p = g_P[i], ap = g_AP[i];
                    g_X[i] += alpha * p;
                    float r = g_R[i] - alpha * ap;
                    g_R[i] = r;
                    rc[k] = r; pc[k] = p;
                    acc += r * r;
                }
            }
            atomicAdd(&sd[c], acc);
            __syncthreads();
            if (tid < BB) atomicAdd(&g_RsB[tid], (double)sd[tid]);
        }
        grid_barrier(PBLOCKS);

        // ---- update2: beta (uses smem-cached Rs_old); P = R + beta P; rotate scalars
        {
            if (tid < BB) {
                double rsn = g_RsB[tid];
                s_a[tid] = (float)rsn / (s_rsold[tid] + 1e-12f);
                if (blockIdx.x == 0) {       // safe: nobody reads RsA/pAP this phase
                    g_RsA[tid] = rsn;
                    g_pAP[tid] = 0.0;
                }
            }
            __syncthreads();
            float beta = s_a[c];
            #pragma unroll
            for (int k = 0; k < 5; k++) {
                int i = gt + k * PTHREADS;
                if (i < NELEM) g_P[i] = rc[k] + beta * pc[k];
            }
            if (blockIdx.x == 0 && tid == 0) {
                int ok = 1;
                for (int q = 0; q < BB; q++)
                    if (g_RsB[q] >= TOL2) { ok = 0; break; }
                if (ok) g_done = 1;
            }
        }
        grid_barrier(PBLOCKS);
        if (*(volatile int*)&g_done) break;   // uniform across all blocks
    }
}

// ---------------- output: out[b][item] = X[item][b] ----------------
__global__ void k_output(float* __restrict__ out) {
    int t = blockIdx.x * blockDim.x + threadIdx.x;
    int b = t >> 14, item = t & 16383;
    out[t] = g_X[item * BB + b];
}

// ---------------- launch: 7 graph nodes total ----------------
extern "C" void kernel_launch(void* const* d_in, const int* in_sizes, int n_in,
                              void* d_out, int out_size) {
    const float* Xb   = (const float*)d_in[0];
    const int*   rows = (const int*)d_in[1];
    const int*   cols = (const int*)d_in[2];
    const float* vals = (const float*)d_in[3];
    int nnz = in_sizes[1];
    if (nnz > MAXNNZ) nnz = MAXNNZ;

    const int ELEM_BLOCKS = NELEM / 256;                  // 4096
    const int NNZ_BLOCKS  = (nnz + 255) / 256;            // ~3907
    const int CSR_BLOCKS  = (NUSERS * 32) / 256;          // 5000

    k_init       <<<ELEM_BLOCKS, 256>>>(Xb);
    k_hist       <<<NNZ_BLOCKS, 256>>>(rows, cols, nnz);
    k_scan       <<<56, 1024>>>();
    k_scatter    <<<NNZ_BLOCKS, 256>>>(rows, cols, vals, nnz);
    k_spmm_csr_rhs<<<CSR_BLOCKS, 256>>>();
    k_cg         <<<PBLOCKS, 256>>>();
    k_output     <<<ELEM_BLOCKS, 256>>>((float*)d_out);
}

// round 5
// speedup vs baseline: 1.2789x; 1.0383x over previous
#include <cuda_runtime.h>

#define NUSERS 40000
#define NITEMS 16384
#define MAXNNZ 1000000
#define BB 64
#define LAMBDA 500.0f
#define MAX_ITER 30
#define TOL2 1e-12   // TOL^2, compare vs Rs (sum of squares)

#define PBLOCKS 444                   // 148 SMs x 3 blocks of 512 threads
#define PTHREADS (PBLOCKS * 512)      // 227328
#define PWARPS   (PTHREADS / 32)      // 7104
#define NELEM    (NITEMS * BB)        // 1048576

// ---------------- device global scratch ----------------
__device__ int    g_row_cnt[NUSERS];
__device__ int    g_row_ptr[NUSERS + 1];
__device__ int    g_row_off[NUSERS];
__device__ int    g_col_cnt[NITEMS];
__device__ int    g_col_ptr[NITEMS + 1];
__device__ int    g_col_off[NITEMS];
__device__ __align__(16) int2 g_csr[MAXNNZ];   // {col, float_bits(val)}
__device__ __align__(16) int2 g_csc[MAXNNZ];   // {row, float_bits(val)}
__device__ int    g_bsum[64];

__device__ float  g_tmp[NUSERS * BB];
__device__ float  g_Xt [NELEM];
__device__ float  g_X  [NELEM];
__device__ float  g_R  [NELEM];
__device__ float  g_P  [NELEM];
__device__ float  g_AP [NELEM];

__device__ double g_RsA[BB];   // Rs_old
__device__ double g_RsB[BB];   // Rs_new
__device__ double g_pAP[BB];
__device__ int    g_done;

// ---------------- grid-wide barrier (sense via generation counter) ----------------
__device__ unsigned g_bar_cnt;
__device__ unsigned g_bar_gen;

__device__ __forceinline__ void grid_barrier(unsigned nblocks) {
    __syncthreads();
    if (threadIdx.x == 0) {
        unsigned gen = *(volatile unsigned*)&g_bar_gen;
        __threadfence();
        if (atomicAdd(&g_bar_cnt, 1u) == nblocks - 1u) {
            g_bar_cnt = 0u;
            __threadfence();
            atomicAdd(&g_bar_gen, 1u);
        } else {
            while (*(volatile unsigned*)&g_bar_gen == gen) { }
        }
        __threadfence();
    }
    __syncthreads();
}

// ---------------- gather of one sparse row into a warp-held float2 ----------------
// idx pairs loaded as aligned int4 (2 nnz per broadcast LDG.128).
__device__ __forceinline__ float2 row_gather(const int2* __restrict__ idx,
                                             const float* __restrict__ V,
                                             int s, int e, int lane) {
    float2 a0 = {0.f,0.f}, a1 = {0.f,0.f}, a2 = {0.f,0.f}, a3 = {0.f,0.f};
    int j = s;
    if ((j & 1) && j < e) {                       // parity peel -> 16B alignment
        int2 p = __ldcs(idx + j);
        float2 q = *(const float2*)(V + p.x * BB + 2 * lane);
        float v = __int_as_float(p.y);
        a0.x += v * q.x; a0.y += v * q.y;
        j++;
    }
    for (; j + 3 < e; j += 4) {
        int4 A = __ldcs((const int4*)(idx + j));
        int4 B = __ldcs((const int4*)(idx + j + 2));
        float2 q0 = *(const float2*)(V + A.x * BB + 2 * lane);
        float2 q1 = *(const float2*)(V + A.z * BB + 2 * lane);
        float2 q2 = *(const float2*)(V + B.x * BB + 2 * lane);
        float2 q3 = *(const float2*)(V + B.z * BB + 2 * lane);
        float v0 = __int_as_float(A.y), v1 = __int_as_float(A.w);
        float v2 = __int_as_float(B.y), v3 = __int_as_float(B.w);
        a0.x += v0*q0.x; a0.y += v0*q0.y;
        a1.x += v1*q1.x; a1.y += v1*q1.y;
        a2.x += v2*q2.x; a2.y += v2*q2.y;
        a3.x += v3*q3.x; a3.y += v3*q3.y;
    }
    if (j + 1 < e) {
        int4 A = __ldcs((const int4*)(idx + j));
        float2 q0 = *(const float2*)(V + A.x * BB + 2 * lane);
        float2 q1 = *(const float2*)(V + A.z * BB + 2 * lane);
        float v0 = __int_as_float(A.y), v1 = __int_as_float(A.w);
        a0.x += v0*q0.x; a0.y += v0*q0.y;
        a1.x += v1*q1.x; a1.y += v1*q1.y;
        j += 2;
    }
    if (j < e) {
        int2 p = __ldcs(idx + j);
        float2 q = *(const float2*)(V + p.x * BB + 2 * lane);
        float v = __int_as_float(p.y);
        a0.x += v*q.x; a0.y += v*q.y;
    }
    return make_float2((a0.x + a1.x) + (a2.x + a3.x),
                       (a0.y + a1.y) + (a2.y + a3.y));
}

// ---------------- tiled transpose + init (1024 blocks x 256) ----------------
// Xb is (64 x 16384) b-major; produce Xt (16384 x 64). 32x32 smem tiles.
__global__ void k_tinit(const float* __restrict__ Xb) {
    __shared__ float tile[32][33];
    int itile = (blockIdx.x & 511) * 32;     // item tile
    int btile = (blockIdx.x >> 9) * 32;      // batch tile (0 or 32)
    int tx = threadIdx.x & 31;
    int ty = threadIdx.x >> 5;               // 0..7
    #pragma unroll
    for (int r = 0; r < 32; r += 8)          // coalesced read along item
        tile[ty + r][tx] = __ldg(&Xb[(btile + ty + r) * NITEMS + itile + tx]);
    __syncthreads();
    #pragma unroll
    for (int r = 0; r < 32; r += 8) {        // coalesced-ish write along b
        int item = itile + ty + r;
        g_Xt[item * BB + btile + tx] = tile[tx][ty + r];
        g_X [item * BB + btile + tx] = 0.0f;
    }
    int gid = blockIdx.x * 256 + threadIdx.x;   // 262144 total
    if (gid < NUSERS) g_row_cnt[gid] = 0;
    if (gid < NITEMS) g_col_cnt[gid] = 0;
    if (gid < BB) { g_RsA[gid] = 0.0; g_RsB[gid] = 0.0; g_pAP[gid] = 0.0; }
    if (gid == 0) g_done = 0;
}

// ---------------- histogram: 4 nnz per thread, 8 independent atomics ----------------
__global__ void k_hist(const int* __restrict__ rows, const int* __restrict__ cols, int nnz) {
    int k4 = (blockIdx.x * blockDim.x + threadIdx.x) * 4;
    if (k4 + 3 < nnz) {
        int4 r = __ldcs((const int4*)(rows + k4));
        int4 c = __ldcs((const int4*)(cols + k4));
        atomicAdd(&g_row_cnt[r.x], 1); atomicAdd(&g_row_cnt[r.y], 1);
        atomicAdd(&g_row_cnt[r.z], 1); atomicAdd(&g_row_cnt[r.w], 1);
        atomicAdd(&g_col_cnt[c.x], 1); atomicAdd(&g_col_cnt[c.y], 1);
        atomicAdd(&g_col_cnt[c.z], 1); atomicAdd(&g_col_cnt[c.w], 1);
    } else {
        for (int k = k4; k < nnz; k++) {
            atomicAdd(&g_row_cnt[__ldcs(rows + k)], 1);
            atomicAdd(&g_col_cnt[__ldcs(cols + k)], 1);
        }
    }
}

// ---------------- fused hierarchical scan (56 resident blocks) ----------------
__global__ void k_scan() {
    __shared__ int wsum[32];
    int b = blockIdx.x;
    bool isRow = (b < 40);
    const int* cnt = isRow ? g_row_cnt : g_col_cnt;
    int* ptr = isRow ? g_row_ptr : g_col_ptr;
    int* off = isRow ? g_row_off : g_col_off;
    int n    = isRow ? NUSERS    : NITEMS;
    int i = (isRow ? b : (b - 40)) * 1024 + threadIdx.x;
    int lane = threadIdx.x & 31, w = threadIdx.x >> 5;

    int v = (i < n) ? cnt[i] : 0;
    int x = v;
    #pragma unroll
    for (int s = 1; s < 32; s <<= 1) {
        int t = __shfl_up_sync(0xffffffffu, x, s);
        if (lane >= s) x += t;
    }
    if (lane == 31) wsum[w] = x;
    __syncthreads();
    if (w == 0) {
        int y = wsum[lane];
        #pragma unroll
        for (int s = 1; s < 32; s <<= 1) {
            int t = __shfl_up_sync(0xffffffffu, y, s);
            if (lane >= s) y += t;
        }
        wsum[lane] = y;
    }
    __syncthreads();
    int incl = x + (w ? wsum[w - 1] : 0);
    int loc_excl = incl - v;
    if (threadIdx.x == 1023) g_bsum[b] = incl;

    grid_barrier(56);

    if (b == 0 && threadIdx.x == 0) {
        int s = 0;
        for (int k = 0; k < 40; k++) { int t = g_bsum[k]; g_bsum[k] = s; s += t; }
        g_row_ptr[NUSERS] = s;
    }
    if (b == 1 && threadIdx.x == 0) {
        int s = 0;
        for (int k = 40; k < 56; k++) { int t = g_bsum[k]; g_bsum[k] = s; s += t; }
        g_col_ptr[NITEMS] = s;
    }

    grid_barrier(56);

    if (i < n) {
        int p = loc_excl + g_bsum[b];
        ptr[i] = p;
        off[i] = p;
    }
}

// ---------------- scatter: 4 nnz per thread, independent atomic chains ----------------
__global__ void k_scatter(const int* __restrict__ rows, const int* __restrict__ cols,
                          const float* __restrict__ vals, int nnz) {
    int k4 = (blockIdx.x * blockDim.x + threadIdx.x) * 4;
    if (k4 + 3 < nnz) {
        int4   r = __ldcs((const int4*)(rows + k4));
        int4   c = __ldcs((const int4*)(cols + k4));
        float4 v = __ldcs((const float4*)(vals + k4));
        int p0 = atomicAdd(&g_row_off[r.x], 1);
        int p1 = atomicAdd(&g_row_off[r.y], 1);
        int p2 = atomicAdd(&g_row_off[r.z], 1);
        int p3 = atomicAdd(&g_row_off[r.w], 1);
        g_csr[p0] = make_int2(c.x, __float_as_int(v.x));
        g_csr[p1] = make_int2(c.y, __float_as_int(v.y));
        g_csr[p2] = make_int2(c.z, __float_as_int(v.z));
        g_csr[p3] = make_int2(c.w, __float_as_int(v.w));
        int q0 = atomicAdd(&g_col_off[c.x], 1);
        int q1 = atomicAdd(&g_col_off[c.y], 1);
        int q2 = atomicAdd(&g_col_off[c.z], 1);
        int q3 = atomicAdd(&g_col_off[c.w], 1);
        g_csc[q0] = make_int2(r.x, __float_as_int(v.x));
        g_csc[q1] = make_int2(r.y, __float_as_int(v.y));
        g_csc[q2] = make_int2(r.z, __float_as_int(v.z));
        g_csc[q3] = make_int2(r.w, __float_as_int(v.w));
    } else {
        for (int k = k4; k < nnz; k++) {
            int rr = __ldcs(rows + k); int cc = __ldcs(cols + k);
            int vb = __float_as_int(__ldcs(vals + k));
            int p = atomicAdd(&g_row_off[rr], 1);
            g_csr[p] = make_int2(cc, vb);
            int q = atomicAdd(&g_col_off[cc], 1);
            g_csc[q] = make_int2(rr, vb);
        }
    }
}

// ---------------- standalone RHS csr pass: tmp = X @ Xt ----------------
__global__ void k_spmm_csr_rhs() {
    int gw   = (blockIdx.x * blockDim.x + threadIdx.x) >> 5;  // 40000 warps
    int lane = threadIdx.x & 31;
    float2 o = row_gather(g_csr, g_Xt, g_row_ptr[gw], g_row_ptr[gw + 1], lane);
    *(float2*)(g_tmp + gw * BB + 2 * lane) = o;
}

// ---------------- persistent CG mega-kernel: 444 blocks x 512 ----------------
__global__ void __launch_bounds__(512, 3) k_cg() {
    __shared__ float sd[BB];
    __shared__ float s_a[BB];        // alpha, then beta
    __shared__ float s_rsold[BB];

    int tid  = threadIdx.x;
    int gt   = blockIdx.x * 512 + tid;
    int gw   = gt >> 5;
    int lane = tid & 31;
    int c0   = 2 * lane;
    int c    = tid & 63;   // PTHREADS is a multiple of 64 -> column fixed per thread

    // ===== RHS csc phase: R0 = P0 = X^T tmp ; RsA = sum(R0^2) =====
    {
        if (tid < BB) sd[tid] = 0.f;
        __syncthreads();
        float accx = 0.f, accy = 0.f;
        for (int row = gw; row < NITEMS; row += PWARPS) {
            float2 o = row_gather(g_csc, g_tmp, g_col_ptr[row], g_col_ptr[row + 1], lane);
            *(float2*)(g_R + row * BB + c0) = o;
            *(float2*)(g_P + row * BB + c0) = o;
            accx += o.x * o.x; accy += o.y * o.y;
        }
        atomicAdd(&sd[c0], accx); atomicAdd(&sd[c0 + 1], accy);
        __syncthreads();
        if (tid < BB) atomicAdd(&g_RsA[tid], (double)sd[tid]);
    }
    grid_barrier(PBLOCKS);

    // ===== 30 CG iterations =====
    for (int it = 0; it < MAX_ITER; it++) {
        // ---- csr phase: tmp = X @ P ; block0 zeroes RsB for this iter
        if (blockIdx.x == 0 && tid < BB) g_RsB[tid] = 0.0;
        for (int row = gw; row < NUSERS; row += PWARPS) {
            float2 o = row_gather(g_csr, g_P, g_row_ptr[row], g_row_ptr[row + 1], lane);
            *(float2*)(g_tmp + row * BB + c0) = o;
        }
        grid_barrier(PBLOCKS);

        // ---- csc phase: AP = X^T tmp + lambda P ; pAP += P.AP
        {
            if (tid < BB) sd[tid] = 0.f;
            __syncthreads();
            float accx = 0.f, accy = 0.f;
            for (int row = gw; row < NITEMS; row += PWARPS) {
                float2 o = row_gather(g_csc, g_tmp, g_col_ptr[row], g_col_ptr[row + 1], lane);
                float2 p = *(const float2*)(g_P + row * BB + c0);
                o.x += LAMBDA * p.x; o.y += LAMBDA * p.y;
                *(float2*)(g_AP + row * BB + c0) = o;
                accx += p.x * o.x; accy += p.y * o.y;
            }
            atomicAdd(&sd[c0], accx); atomicAdd(&sd[c0 + 1], accy);
            __syncthreads();
            if (tid < BB) atomicAdd(&g_pAP[tid], (double)sd[tid]);
        }
        grid_barrier(PBLOCKS);

        // ---- update1: alpha; X += aP; R -= a AP; RsB = sum(R^2)
        float rc[5], pc[5];
        {
            if (tid < BB) {
                float rso = (float)g_RsA[tid];
                s_a[tid] = rso / ((float)g_pAP[tid] + 1e-12f);
                s_rsold[tid] = rso;
                sd[tid] = 0.f;
            }
            __syncthreads();
            float alpha = s_a[c];
            float acc = 0.f;
            #pragma unroll
            for (int k = 0; k < 5; k++) {
                int i = gt + k * PTHREADS;
                if (i < NELEM) {
                    float p = g_P[i], ap = g_AP[i];
                    g_X[i] += alpha * p;
                    float r = g_R[i] - alpha * ap;
                    g_R[i] = r;
                    rc[k] = r; pc[k] = p;
                    acc += r * r;
                }
            }
            atomicAdd(&sd[c], acc);
            __syncthreads();
            if (tid < BB) atomicAdd(&g_RsB[tid], (double)sd[tid]);
        }
        grid_barrier(PBLOCKS);

        // ---- update2: beta; P = R + beta P; rotate scalars in block0
        {
            if (tid < BB) {
                double rsn = g_RsB[tid];
                s_a[tid] = (float)rsn / (s_rsold[tid] + 1e-12f);
                if (blockIdx.x == 0) {
                    g_RsA[tid] = rsn;
                    g_pAP[tid] = 0.0;
                }
            }
            __syncthreads();
            float beta = s_a[c];
            #pragma unroll
            for (int k = 0; k < 5; k++) {
                int i = gt + k * PTHREADS;
                if (i < NELEM) g_P[i] = rc[k] + beta * pc[k];
            }
            if (blockIdx.x == 0 && tid == 0) {
                int ok = 1;
                for (int q = 0; q < BB; q++)
                    if (g_RsB[q] >= TOL2) { ok = 0; break; }
                if (ok) g_done = 1;
            }
        }
        grid_barrier(PBLOCKS);
        if (*(volatile int*)&g_done) break;   // uniform across all blocks
    }
}

// ---------------- output: out[b][item] = X[item][b] ----------------
__global__ void k_output(float* __restrict__ out) {
    int t = blockIdx.x * blockDim.x + threadIdx.x;
    int b = t >> 14, item = t & 16383;
    out[t] = g_X[item * BB + b];
}

// ---------------- launch: 7 graph nodes total ----------------
extern "C" void kernel_launch(void* const* d_in, const int* in_sizes, int n_in,
                              void* d_out, int out_size) {
    const float* Xb   = (const float*)d_in[0];
    const int*   rows = (const int*)d_in[1];
    const int*   cols = (const int*)d_in[2];
    const float* vals = (const float*)d_in[3];
    int nnz = in_sizes[1];
    if (nnz > MAXNNZ) nnz = MAXNNZ;

    const int ELEM_BLOCKS = NELEM / 256;                  // 4096
    const int NNZ4_BLOCKS = (nnz + 1023) / 1024;          // 4 nnz per thread
    const int CSR_BLOCKS  = (NUSERS * 32) / 256;          // 5000

    k_tinit       <<<1024, 256>>>(Xb);
    k_hist        <<<NNZ4_BLOCKS, 256>>>(rows, cols, nnz);
    k_scan        <<<56, 1024>>>();
    k_scatter     <<<NNZ4_BLOCKS, 256>>>(rows, cols, vals, nnz);
    k_spmm_csr_rhs<<<CSR_BLOCKS, 256>>>();
    k_cg          <<<PBLOCKS, 512>>>();
    k_output      <<<ELEM_BLOCKS, 256>>>((float*)d_out);
}